// round 2
// baseline (speedup 1.0000x reference)
#include <cuda_runtime.h>
#include <cstdint>

// NodePropagatorSparse: out[b,e,0:256]   = node_states[b, edge_src[e], :]
//                       out[b,e,256:512] = node_states[b, edge_tgt[e], :]
// B=4, N=10000, E=160000, D=256. node_states fp32.
// Indices: JAX default config demotes int64 -> int32, so read as int32.

#define B_DIM 4
#define N_DIM 10000
#define E_DIM 160000
#define D_DIM 256
#define D4    (D_DIM / 4)        // 64 float4 per D-row
#define ROW4  (2 * D4)           // 128 float4 per output (b,e) row

__global__ __launch_bounds__(128, 16)
void node_prop_gather_kernel(const float4* __restrict__ ns4,   // [B, N, D4]
                             const int* __restrict__ src,      // [E] int32
                             const int* __restrict__ tgt,      // [E] int32
                             float4* __restrict__ out4)        // [B, E, ROW4]
{
    const int e = blockIdx.x;
    const int t = threadIdx.x;          // 0..127
    const int half = t >> 6;            // 0 = src half, 1 = tgt half
    const int col  = t & 63;            // float4 column within the D-row

    const int idx = half ? tgt[e] : src[e];   // broadcast load per half-block

    const float4* src_row = ns4 + (size_t)idx * D4 + col;          // b=0 row base
    float4*       dst     = out4 + (size_t)e * ROW4 + half * D4 + col;

    // b-loop unrolled: 4 independent 16B loads + stores (MLP=4)
    float4 v0 = src_row[0 * (size_t)N_DIM * D4];
    float4 v1 = src_row[1 * (size_t)N_DIM * D4];
    float4 v2 = src_row[2 * (size_t)N_DIM * D4];
    float4 v3 = src_row[3 * (size_t)N_DIM * D4];

    dst[0 * (size_t)E_DIM * ROW4] = v0;
    dst[1 * (size_t)E_DIM * ROW4] = v1;
    dst[2 * (size_t)E_DIM * ROW4] = v2;
    dst[3 * (size_t)E_DIM * ROW4] = v3;
}

extern "C" void kernel_launch(void* const* d_in, const int* in_sizes, int n_in,
                              void* d_out, int out_size)
{
    const float4* ns4  = (const float4*)d_in[0];
    const int*    src  = (const int*)d_in[1];
    const int*    tgt  = (const int*)d_in[2];
    float4*       out4 = (float4*)d_out;

    node_prop_gather_kernel<<<E_DIM, 128>>>(ns4, src, tgt, out4);
}

// round 3
// speedup vs baseline: 1.1111x; 1.1111x over previous
#include <cuda_runtime.h>
#include <cstdint>

// NodePropagatorSparse: out[b,e,0:256]   = node_states[b, edge_src[e], :]
//                       out[b,e,256:512] = node_states[b, edge_tgt[e], :]
// B=4, N=10000, E=160000, D=256. node_states fp32, indices int32 (JAX x64-off).
//
// R3: streaming stores (__stcs) so the 1.31GB output stream is evict-first in
// L2, keeping the 41MB gather source resident -> cuts ~0.36GB of DRAM re-reads.

#define B_DIM 4
#define N_DIM 10000
#define E_DIM 160000
#define D_DIM 256
#define D4    (D_DIM / 4)        // 64 float4 per D-row
#define ROW4  (2 * D4)           // 128 float4 per output (b,e) row

__global__ __launch_bounds__(128, 16)
void node_prop_gather_kernel(const float4* __restrict__ ns4,   // [B, N, D4]
                             const int* __restrict__ src,      // [E] int32
                             const int* __restrict__ tgt,      // [E] int32
                             float4* __restrict__ out4)        // [B, E, ROW4]
{
    const int e = blockIdx.x;
    const int t = threadIdx.x;          // 0..127
    const int half = t >> 6;            // 0 = src half, 1 = tgt half
    const int col  = t & 63;            // float4 column within the D-row

    const int idx = half ? tgt[e] : src[e];   // broadcast load per half-block

    const float4* src_row = ns4 + (size_t)idx * D4 + col;          // b=0 row base
    float4*       dst     = out4 + (size_t)e * ROW4 + half * D4 + col;

    // b-loop unrolled: 4 independent 16B loads (default caching: keep in L2)
    float4 v0 = src_row[0 * (size_t)N_DIM * D4];
    float4 v1 = src_row[1 * (size_t)N_DIM * D4];
    float4 v2 = src_row[2 * (size_t)N_DIM * D4];
    float4 v3 = src_row[3 * (size_t)N_DIM * D4];

    // Streaming stores: evict-first in L2, protect the gather working set.
    __stcs(&dst[0 * (size_t)E_DIM * ROW4], v0);
    __stcs(&dst[1 * (size_t)E_DIM * ROW4], v1);
    __stcs(&dst[2 * (size_t)E_DIM * ROW4], v2);
    __stcs(&dst[3 * (size_t)E_DIM * ROW4], v3);
}

extern "C" void kernel_launch(void* const* d_in, const int* in_sizes, int n_in,
                              void* d_out, int out_size)
{
    const float4* ns4  = (const float4*)d_in[0];
    const int*    src  = (const int*)d_in[1];
    const int*    tgt  = (const int*)d_in[2];
    float4*       out4 = (float4*)d_out;

    node_prop_gather_kernel<<<E_DIM, 128>>>(ns4, src, tgt, out4);
}